// round 4
// baseline (speedup 1.0000x reference)
#include <cuda_runtime.h>

#define NUM_SEG   32
#define MUL       128
#define D         3
#define NUM_PATHS 64
#define SEG_ELEMS (MUL * D)              // 384 floats per segment
#define ROW_ELEMS (NUM_SEG * SEG_ELEMS)  // 12288 floats per batch row

// Path schedule (computed each launch by ftp3_setup; deterministic, no allocs).
__device__ int g_order[NUM_PATHS];        // paths sorted by idx2
__device__ int g_off0[NUM_PATHS];         // idx0[order[q]] * SEG_ELEMS
__device__ int g_outoff[NUM_PATHS];       // if q ends its segment: s*SEG_ELEMS, else -1
__device__ int g_empty[NUM_SEG];          // segments with zero paths
__device__ int g_nempty;

__global__ void ftp3_setup(const int* __restrict__ idx0,
                           const int* __restrict__ idx2)
{
    if (threadIdx.x != 0 || blockIdx.x != 0) return;
    int cnt[NUM_SEG];
    #pragma unroll
    for (int s = 0; s < NUM_SEG; ++s) cnt[s] = 0;
    for (int p = 0; p < NUM_PATHS; ++p) cnt[idx2[p]]++;

    int ptr = 0, ne = 0;
    int start[NUM_SEG];
    for (int s = 0; s < NUM_SEG; ++s) {
        start[s] = ptr;
        if (cnt[s] == 0) g_empty[ne++] = s * SEG_ELEMS;
        ptr += cnt[s];
    }
    g_nempty = ne;

    int cur[NUM_SEG];
    #pragma unroll
    for (int s = 0; s < NUM_SEG; ++s) cur[s] = start[s];
    for (int p = 0; p < NUM_PATHS; ++p) {
        const int s = idx2[p];
        const int q = cur[s]++;
        g_order[q]  = p;
        g_off0[q]   = idx0[p] * SEG_ELEMS;
        // marked below once counts are final
    }
    for (int s = 0; s < NUM_SEG; ++s) {
        for (int q = start[s]; q < start[s] + cnt[s]; ++q)
            g_outoff[q] = (q == start[s] + cnt[s] - 1) ? s * SEG_ELEMS : -1;
    }
}

__global__ __launch_bounds__(128)
void ftp3_main(const float* __restrict__ x0,
               const float* __restrict__ x1,
               const float* __restrict__ coeff,
               const int*   __restrict__ idx1,
               float*       __restrict__ out)
{
    // M padded to 12 floats per path -> 3x LDS.128 per path.
    __shared__ __align__(16) float M[NUM_PATHS * 12];
    __shared__ int s_off0[NUM_PATHS];
    __shared__ int s_outoff[NUM_PATHS];

    const int t = threadIdx.x;                // one u per thread
    const int b = blockIdx.x;                 // one batch row per CTA

    if (t < NUM_PATHS) {
        const int q = t;
        const int p = g_order[q];
        s_off0[q]   = g_off0[q];
        s_outoff[q] = g_outoff[q];
        const float* c   = coeff + p * 27;                         // [i][j][k]
        const float* x1b = x1 + (size_t)b * (NUM_SEG * D) + idx1[p] * D;
        const float j0 = x1b[0], j1 = x1b[1], j2 = x1b[2];
        #pragma unroll
        for (int i = 0; i < 3; ++i)
            #pragma unroll
            for (int k = 0; k < 3; ++k)
                M[q * 12 + i * 3 + k] =
                    j0 * c[i * 9 + 0 * 3 + k] +
                    j1 * c[i * 9 + 1 * 3 + k] +
                    j2 * c[i * 9 + 2 * 3 + k];
        M[q * 12 +  9] = 0.f;
        M[q * 12 + 10] = 0.f;
        M[q * 12 + 11] = 0.f;
    }
    __syncthreads();

    const float*  x0b  = x0  + (size_t)b * ROW_ELEMS;
    float*        outb = out + (size_t)b * ROW_ELEMS;
    const float4* M4   = (const float4*)M;
    const int u3 = t * 3;

    // Flat loop over paths in segment-sorted order; register accumulation,
    // direct GMEM write at each segment boundary.
    float f0 = 0.f, f1 = 0.f, f2 = 0.f;
    #pragma unroll 4
    for (int q = 0; q < NUM_PATHS; ++q) {
        const float* xs = x0b + s_off0[q] + u3;
        const float a0 = xs[0];
        const float a1 = xs[1];
        const float a2 = xs[2];
        const float4 m0 = M4[q * 3 + 0];   // M00 M01 M02 M10
        const float4 m1 = M4[q * 3 + 1];   // M11 M12 M20 M21
        const float4 m2 = M4[q * 3 + 2];   // M22 - - -
        f0 += a0 * m0.x + a1 * m0.w + a2 * m1.z;
        f1 += a0 * m0.y + a1 * m1.x + a2 * m1.w;
        f2 += a0 * m0.z + a1 * m1.y + a2 * m2.x;
        const int oo = s_outoff[q];
        if (oo >= 0) {
            float* o = outb + oo + u3;
            o[0] = f0; o[1] = f1; o[2] = f2;
            f0 = 0.f; f1 = 0.f; f2 = 0.f;
        }
    }

    // Zero-fill segments that received no paths (output buffer is poisoned).
    const int ne = g_nempty;
    for (int e = 0; e < ne; ++e) {
        float* o = outb + g_empty[e] + u3;
        o[0] = 0.f; o[1] = 0.f; o[2] = 0.f;
    }
}

extern "C" void kernel_launch(void* const* d_in, const int* in_sizes, int n_in,
                              void* d_out, int out_size)
{
    const float* x0    = (const float*)d_in[0];  // (2048, 12288)
    const float* x1    = (const float*)d_in[1];  // (2048, 96)
    const float* coeff = (const float*)d_in[2];  // (64, 27)
    const int*   idx0  = (const int*)d_in[3];
    const int*   idx1  = (const int*)d_in[4];
    const int*   idx2  = (const int*)d_in[5];
    float*       out   = (float*)d_out;          // (2048, 12288)

    const int batch = in_sizes[0] / ROW_ELEMS;   // 2048

    ftp3_setup<<<1, 32>>>(idx0, idx2);
    ftp3_main<<<batch, 128>>>(x0, x1, coeff, idx1, out);
}